// round 1
// baseline (speedup 1.0000x reference)
#include <cuda_runtime.h>
#include <stdint.h>

// FP32 bit-pulse -> FP8 E4M3 bit-pulse converter.
// Input:  N*32 floats, each 0.0/1.0, layout per value [S, E7..E0, M22..M0] (MSB first)
// Output: N*8  floats, layout per value [S, E3..E0, M2..M0]
//
// Strategy: lane l of a warp loads float (v*32 + l); ballot of (f > 0.5) followed
// by __brev reconstructs the IEEE-754 fp32 bit pattern of value v directly
// (bit31 = S, bits30..23 = exponent, bits22..0 = mantissa). A warp loops over 32
// values with perfectly coalesced 128B loads; lane i keeps word i; then each
// lane converts its own word and writes 8 contiguous floats (2x STG.128).

__global__ void __launch_bounds__(256)
fp32_to_fp8_pulse_kernel(const float* __restrict__ in,
                         float* __restrict__ out,
                         int nvals)
{
    const int lane    = threadIdx.x & 31;
    const int warp_id = (blockIdx.x * blockDim.x + threadIdx.x) >> 5;
    const int base    = warp_id * 32;           // 32 values per warp
    if (base >= nvals) return;

    const float* p = in + (size_t)base * 32;

    // Gather: iteration i reconstructs value (base + i); lane i keeps it.
    uint32_t word = 0;
#pragma unroll
    for (int i = 0; i < 32; i++) {
        float f = __ldg(&p[i * 32 + lane]);
        uint32_t b = __ballot_sync(0xFFFFFFFFu, f > 0.5f);
        if (lane == i) word = b;
    }
    word = __brev(word);   // now a standard IEEE fp32 bit pattern

    const uint32_t s    = word >> 31;
    const uint32_t exp  = (word >> 23) & 0xFFu;
    const uint32_t mant = word & 0x7FFFFFu;

    // ---- normal path: fp8_exp = exp - 120, RNE round 23 -> 3 mantissa bits ----
    uint32_t kept  = mant >> 20;
    uint32_t R     = (mant >> 19) & 1u;
    uint32_t S     = (mant & 0x7FFFFu) ? 1u : 0u;
    uint32_t L     = kept & 1u;
    uint32_t mr    = kept + (R & (S | L));
    uint32_t carry = mr >> 3;
    uint32_t mant_norm = carry ? 0u : (mr & 7u);
    int exp_norm = (int)exp - 120 + (int)carry;

    // ---- subnormal path (117 <= exp <= 120): shift 1.mant right, RNE ----
    uint32_t full = (1u << 23) | mant;
    int sh = 141 - (int)exp;
    sh = sh < 1 ? 1 : (sh > 24 ? 24 : sh);
    uint32_t kept_s = full >> sh;
    uint32_t Rs = (full >> (sh - 1)) & 1u;
    uint32_t Ss = (full & ((1u << (sh - 1)) - 1u)) ? 1u : 0u;
    uint32_t Ls = kept_s & 1u;
    uint32_t ms = kept_s + (Rs & (Ss | Ls));
    uint32_t sub_exp  = (ms >= 8u) ? 1u : 0u;
    uint32_t sub_mant = (ms >= 8u) ? 0u : ms;

    // ---- select overflow / subnormal / underflow / normal ----
    uint32_t exp8, mant8;
    if (exp > 134u) {
        exp8 = 15u; mant8 = 6u;
    } else if (exp >= 117u) {          // 117..120 given not >134 handled below
        if (exp <= 120u) { exp8 = sub_exp; mant8 = sub_mant; }
        else             { exp8 = (uint32_t)exp_norm; mant8 = mant_norm; }
    } else {
        exp8 = 0u; mant8 = 0u;         // underflow
    }

    // ---- emit 8 bit-pulses: [S, E3..E0, M2..M0] ----
    float4 o0 = make_float4((float)s,
                            (float)((exp8 >> 3) & 1u),
                            (float)((exp8 >> 2) & 1u),
                            (float)((exp8 >> 1) & 1u));
    float4 o1 = make_float4((float)(exp8 & 1u),
                            (float)((mant8 >> 2) & 1u),
                            (float)((mant8 >> 1) & 1u),
                            (float)(mant8 & 1u));

    float4* op = reinterpret_cast<float4*>(out + (size_t)(base + lane) * 8);
    op[0] = o0;
    op[1] = o1;
}

extern "C" void kernel_launch(void* const* d_in, const int* in_sizes, int n_in,
                              void* d_out, int out_size)
{
    const float* in  = (const float*)d_in[0];
    float*       out = (float*)d_out;
    const int nvals  = in_sizes[0] / 32;       // 2,097,152

    const int threads = 256;                   // 8 warps -> 256 values per block
    const int values_per_block = threads;      // one value per thread
    const int blocks = (nvals + values_per_block - 1) / values_per_block;

    fp32_to_fp8_pulse_kernel<<<blocks, threads>>>(in, out, nvals);
}

// round 2
// speedup vs baseline: 1.0048x; 1.0048x over previous
#include <cuda_runtime.h>
#include <stdint.h>

// FP32 bit-pulse -> FP8 E4M3 bit-pulse converter.
// Input:  N*32 floats, each 0.0/1.0, layout per value [S, E7..E0, M22..M0] (MSB first)
// Output: N*8  floats, layout per value [S, E3..E0, M2..M0]
//
// Strategy: lane l of a warp loads float (v*32 + l); ballot of (f > 0.5) followed
// by __brev reconstructs the IEEE-754 fp32 bit pattern of value v directly.
// Round-2 change: all 32 gather loads are issued into a register array BEFORE
// the ballot loop, so the warp keeps 32 LDGs in flight (MLP=32) instead of ~6,
// hiding DRAM latency inside the warp rather than relying purely on occupancy.

__global__ void __launch_bounds__(256)
fp32_to_fp8_pulse_kernel(const float* __restrict__ in,
                         float* __restrict__ out,
                         int nvals)
{
    const int lane    = threadIdx.x & 31;
    const int warp_id = (blockIdx.x * blockDim.x + threadIdx.x) >> 5;
    const int base    = warp_id * 32;           // 32 values per warp
    if (base >= nvals) return;

    const float* p = in + (size_t)base * 32;

    // Phase 1: batch all 32 loads (front-batched LDG -> high MLP).
    float f[32];
#pragma unroll
    for (int i = 0; i < 32; i++) {
        f[i] = __ldg(&p[i * 32 + lane]);
    }

    // Phase 2: 32 ballots; lane i keeps word i.
    uint32_t word = 0;
#pragma unroll
    for (int i = 0; i < 32; i++) {
        uint32_t b = __ballot_sync(0xFFFFFFFFu, f[i] > 0.5f);
        if (lane == i) word = b;
    }
    word = __brev(word);   // now a standard IEEE fp32 bit pattern

    const uint32_t s    = word >> 31;
    const uint32_t exp  = (word >> 23) & 0xFFu;
    const uint32_t mant = word & 0x7FFFFFu;

    // ---- normal path: fp8_exp = exp - 120, RNE round 23 -> 3 mantissa bits ----
    uint32_t kept  = mant >> 20;
    uint32_t R     = (mant >> 19) & 1u;
    uint32_t S     = (mant & 0x7FFFFu) ? 1u : 0u;
    uint32_t L     = kept & 1u;
    uint32_t mr    = kept + (R & (S | L));
    uint32_t carry = mr >> 3;
    uint32_t mant_norm = carry ? 0u : (mr & 7u);
    int exp_norm = (int)exp - 120 + (int)carry;

    // ---- subnormal path (117 <= exp <= 120): shift 1.mant right, RNE ----
    uint32_t full = (1u << 23) | mant;
    int sh = 141 - (int)exp;
    sh = sh < 1 ? 1 : (sh > 24 ? 24 : sh);
    uint32_t kept_s = full >> sh;
    uint32_t Rs = (full >> (sh - 1)) & 1u;
    uint32_t Ss = (full & ((1u << (sh - 1)) - 1u)) ? 1u : 0u;
    uint32_t Ls = kept_s & 1u;
    uint32_t ms = kept_s + (Rs & (Ss | Ls));
    uint32_t sub_exp  = (ms >= 8u) ? 1u : 0u;
    uint32_t sub_mant = (ms >= 8u) ? 0u : ms;

    // ---- select overflow / subnormal / underflow / normal ----
    uint32_t exp8, mant8;
    if (exp > 134u) {
        exp8 = 15u; mant8 = 6u;
    } else if (exp >= 117u) {
        if (exp <= 120u) { exp8 = sub_exp; mant8 = sub_mant; }
        else             { exp8 = (uint32_t)exp_norm; mant8 = mant_norm; }
    } else {
        exp8 = 0u; mant8 = 0u;         // underflow
    }

    // ---- emit 8 bit-pulses: [S, E3..E0, M2..M0] ----
    float4 o0 = make_float4((float)s,
                            (float)((exp8 >> 3) & 1u),
                            (float)((exp8 >> 2) & 1u),
                            (float)((exp8 >> 1) & 1u));
    float4 o1 = make_float4((float)(exp8 & 1u),
                            (float)((mant8 >> 2) & 1u),
                            (float)((mant8 >> 1) & 1u),
                            (float)(mant8 & 1u));

    float4* op = reinterpret_cast<float4*>(out + (size_t)(base + lane) * 8);
    op[0] = o0;
    op[1] = o1;
}

extern "C" void kernel_launch(void* const* d_in, const int* in_sizes, int n_in,
                              void* d_out, int out_size)
{
    const float* in  = (const float*)d_in[0];
    float*       out = (float*)d_out;
    const int nvals  = in_sizes[0] / 32;       // 2,097,152

    const int threads = 256;                   // 8 warps -> 256 values per block
    const int values_per_block = threads;      // one value per thread
    const int blocks = (nvals + values_per_block - 1) / values_per_block;

    fp32_to_fp8_pulse_kernel<<<blocks, threads>>>(in, out, nvals);
}